// round 15
// baseline (speedup 1.0000x reference)
#include <cuda_runtime.h>
#include <cuda_bf16.h>
#include <cstdint>

// Potts energy: out[b] = sum_{i<=j} W[i,j] * [(1-x_i)(1-x_j) + x_i*x_j]
// Symmetrize: S_ii = W_ii, S_ij = S_ji = W_ij/2 (i<j). Exactly:
//   E(b) = sum(S) - 2 r^T x_b + 2 x_b^T S x_b,   r = S*1
// Dense (no mask) x^T S x via tensor cores: bf16 hi/lo split,
// D = Xh*Sh + Xh*Sl + Xl*Sh with f32 accum (mma.sync m16n8k16 -> HMMA,
// arch-generic PTX since tcgen05 is unavailable under this toolchain target).
// main: 128 CTAs (16 j-tiles x 8 k-chunks of 128), 256 thr; S symmetric so
// smem S[n][k] row-major IS the col-major B operand.

#define Bb    128
#define Nn    1024
#define MAIN_CTAS  128
#define PREPS_CTAS 136
#define RB    272     // smem row stride bytes (136 bf16): 16B-aligned, ldmatrix conflict-free

__device__ __nv_bfloat16 g_Sh[Nn * Nn];
__device__ __nv_bfloat16 g_Sl[Nn * Nn];
__device__ __nv_bfloat16 g_Xh[Bb * Nn];
__device__ __nv_bfloat16 g_Xl[Bb * Nn];
__device__ float         g_Vt[Nn * Bb];
__device__ float         g_accum[Bb];
__device__ unsigned int  g_count;

// ---------------- kernel 1: V -> Vt (f32) + Xh/Xl (bf16 split) ----------------
__global__ void prep_v(const float* __restrict__ V) {
    __shared__ float ts[32][33];
    const int bx = blockIdx.x, by = blockIdx.y;
    const int tx = threadIdx.x, ty = threadIdx.y;
    #pragma unroll
    for (int k = 0; k < 32; k += 8) {
        int b = by * 32 + ty + k, n = bx * 32 + tx;
        float v = V[(size_t)b * Nn + n];
        ts[ty + k][tx] = v;
        __nv_bfloat16 h = __float2bfloat16(v);
        g_Xh[(size_t)b * Nn + n] = h;
        g_Xl[(size_t)b * Nn + n] = __float2bfloat16(v - __bfloat162float(h));
    }
    __syncthreads();
    #pragma unroll
    for (int k = 0; k < 32; k += 8)
        g_Vt[(size_t)(bx * 32 + ty + k) * Bb + by * 32 + tx] = ts[tx][ty + k];
}

// ------- kernel 2: build Sh/Sl; fold sum(S) - 2 r^T x into g_accum -------
__global__ void __launch_bounds__(256)
prep_s(const float* __restrict__ W) {
    __shared__ float ws[64][65];
    __shared__ float sv[64][65];
    __shared__ float rp[128];
    __shared__ float bs;

    const int tid = threadIdx.x;
    int k = blockIdx.x, ti = 0;
    while (k >= 16 - ti) { k -= 16 - ti; ti++; }
    const int tj = ti + k;
    const int r0 = ti * 64, c0 = tj * 64;
    const bool diag = (ti == tj);

    #pragma unroll
    for (int it = 0; it < 16; it++) {
        int idx = it * 256 + tid, r = idx >> 6, c = idx & 63;
        ws[r][c] = W[(size_t)(r0 + r) * Nn + c0 + c];
    }
    __syncthreads();

    #pragma unroll
    for (int it = 0; it < 16; it++) {
        int idx = it * 256 + tid, r = idx >> 6, c = idx & 63;
        float s;
        if (diag) s = (r == c) ? ws[r][r] : ((r < c) ? 0.5f * ws[r][c] : 0.5f * ws[c][r]);
        else      s = 0.5f * ws[r][c];
        sv[r][c] = s;
        __nv_bfloat16 h = __float2bfloat16(s);
        size_t o = (size_t)(r0 + r) * Nn + c0 + c;
        g_Sh[o] = h;
        g_Sl[o] = __float2bfloat16(s - __bfloat162float(h));
    }
    __syncthreads();

    if (!diag) {
        #pragma unroll
        for (int it = 0; it < 16; it++) {
            int idx = it * 256 + tid, r = idx >> 6, c = idx & 63;
            float s = sv[c][r];
            __nv_bfloat16 h = __float2bfloat16(s);
            size_t o = (size_t)(c0 + r) * Nn + r0 + c;
            g_Sh[o] = h;
            g_Sl[o] = __float2bfloat16(s - __bfloat162float(h));
        }
    }

    if (tid < 64) {
        float s = 0.0f;
        #pragma unroll
        for (int c = 0; c < 64; c++) s += sv[tid][c];
        rp[tid] = s;
    } else if (tid < 128) {
        int c = tid - 64;
        float s = 0.0f;
        if (!diag) {
            #pragma unroll
            for (int r = 0; r < 64; r++) s += sv[r][c];
        }
        rp[tid] = s;
    }
    __syncthreads();
    if (tid < 32) {
        float v = rp[tid] + rp[tid + 32] + rp[tid + 64] + rp[tid + 96];
        #pragma unroll
        for (int o = 16; o > 0; o >>= 1) v += __shfl_down_sync(0xffffffffu, v, o);
        if (tid == 0) bs = v;
    }
    __syncthreads();

    if (tid < Bb) {
        float acc = 0.0f;
        #pragma unroll 8
        for (int t = 0; t < 64; t++)
            acc = fmaf(rp[t], g_Vt[(size_t)(r0 + t) * Bb + tid], acc);
        if (!diag) {
            #pragma unroll 8
            for (int t = 0; t < 64; t++)
                acc = fmaf(rp[64 + t], g_Vt[(size_t)(c0 + t) * Bb + tid], acc);
        }
        atomicAdd(&g_accum[tid], bs - 2.0f * acc);
    }
}

// ---------------- kernel 3: HMMA main ----------------
__device__ __forceinline__ uint32_t smem_u32(const void* p) {
    uint32_t a;
    asm("{ .reg .u64 t; cvta.to.shared.u64 t, %1; cvt.u32.u64 %0, t; }"
        : "=r"(a) : "l"(p));
    return a;
}
__device__ __forceinline__ void ldsm4(uint32_t* r, uint32_t addr) {
    asm volatile("ldmatrix.sync.aligned.m8n8.x4.shared.b16 {%0,%1,%2,%3}, [%4];"
                 : "=r"(r[0]), "=r"(r[1]), "=r"(r[2]), "=r"(r[3]) : "r"(addr));
}
__device__ __forceinline__ void mma16816(float* d, const uint32_t* a, const uint32_t* b) {
    asm volatile(
        "mma.sync.aligned.m16n8k16.row.col.f32.bf16.bf16.f32 "
        "{%0,%1,%2,%3}, {%4,%5,%6,%7}, {%8,%9}, {%0,%1,%2,%3};"
        : "+f"(d[0]), "+f"(d[1]), "+f"(d[2]), "+f"(d[3])
        : "r"(a[0]), "r"(a[1]), "r"(a[2]), "r"(a[3]), "r"(b[0]), "r"(b[1]));
}

#define SM_AH 0
#define SM_AL 34816
#define SM_BH 69632
#define SM_BL 87040
#define SM_TOT 104448

extern __shared__ char smem[];

__global__ void __launch_bounds__(256, 1)
potts_mma(float* __restrict__ out) {
    const int tid  = threadIdx.x;
    const int wid  = tid >> 5;
    const int lane = tid & 31;
    const int jt  = blockIdx.x & 15;
    const int kc  = blockIdx.x >> 4;
    const int gj0 = jt * 64;
    const int k0  = kc * 128;

    // ---- stage Xh/Xl [128 b][128 k], Sh/Sl [64 n][128 k] into padded smem ----
    {
        const char* srcXh = (const char*)g_Xh + (size_t)k0 * 2;
        const char* srcXl = (const char*)g_Xl + (size_t)k0 * 2;
        const char* srcSh = (const char*)g_Sh + ((size_t)gj0 * Nn + k0) * 2;
        const char* srcSl = (const char*)g_Sl + ((size_t)gj0 * Nn + k0) * 2;
        #pragma unroll
        for (int it = 0; it < 8; it++) {
            int idx = it * 256 + tid;          // 2048 rows*16
            int r = idx >> 4, c = idx & 15;
            uint4 vh = *(const uint4*)(srcXh + (size_t)r * (Nn * 2) + c * 16);
            uint4 vl = *(const uint4*)(srcXl + (size_t)r * (Nn * 2) + c * 16);
            *(uint4*)(smem + SM_AH + r * RB + c * 16) = vh;
            *(uint4*)(smem + SM_AL + r * RB + c * 16) = vl;
        }
        #pragma unroll
        for (int it = 0; it < 4; it++) {
            int idx = it * 256 + tid;          // 1024
            int r = idx >> 4, c = idx & 15;
            uint4 vh = *(const uint4*)(srcSh + (size_t)r * (Nn * 2) + c * 16);
            uint4 vl = *(const uint4*)(srcSl + (size_t)r * (Nn * 2) + c * 16);
            *(uint4*)(smem + SM_BH + r * RB + c * 16) = vh;
            *(uint4*)(smem + SM_BL + r * RB + c * 16) = vl;
        }
    }
    __syncthreads();

    // ---- ldmatrix lane addressing ----
    const uint32_t sbase = smem_u32(smem);
    const int m0 = wid * 16;                    // warp's 16 b-rows
    const uint32_t aoff = (uint32_t)(m0 + (lane & 7) + ((lane >> 3) & 1) * 8) * RB
                        + ((lane >> 4) & 1) * 16;
    const uint32_t addrAh = sbase + SM_AH + aoff;
    const uint32_t addrAl = sbase + SM_AL + aoff;
    const uint32_t boff = (uint32_t)(((lane >> 4) & 1) * 8 + (lane & 7)) * RB
                        + ((lane >> 3) & 1) * 16;
    const uint32_t addrBh = sbase + SM_BH + boff;
    const uint32_t addrBl = sbase + SM_BL + boff;

    // ---- mainloop: D[16b][64n] += Xh*Sh + Xh*Sl + Xl*Sh over K=128 ----
    float d[8][4] = {};
    #pragma unroll 2
    for (int ks = 0; ks < 8; ks++) {
        const uint32_t kb = ks * 32;
        uint32_t ah[4], al[4];
        ldsm4(ah, addrAh + kb);
        ldsm4(al, addrAl + kb);
        #pragma unroll
        for (int ntp = 0; ntp < 4; ntp++) {
            uint32_t bh[4], bl[4];
            ldsm4(bh, addrBh + (uint32_t)ntp * (16 * RB) + kb);
            ldsm4(bl, addrBl + (uint32_t)ntp * (16 * RB) + kb);
            mma16816(d[2 * ntp],     ah, bh);
            mma16816(d[2 * ntp + 1], ah, bh + 2);
            mma16816(d[2 * ntp],     ah, bl);
            mma16816(d[2 * ntp + 1], ah, bl + 2);
            mma16816(d[2 * ntp],     al, bh);
            mma16816(d[2 * ntp + 1], al, bh + 2);
        }
    }

    // ---- epilogue: E_quad(b) += 2 * sum_n D[b][n] * x[b][n] ----
    // accum layout: c0,c1 -> row lane/4, cols 2(lane%4)+{0,1}; c2,c3 -> row+8
    const int b_lo = m0 + (lane >> 2);
    const int b_hi = b_lo + 8;
    float s0 = 0.0f, s1 = 0.0f;
    #pragma unroll
    for (int nt = 0; nt < 8; nt++) {
        int n0 = gj0 + nt * 8 + 2 * (lane & 3);
        float x00 = g_Vt[(size_t)n0 * Bb + b_lo];
        float x01 = g_Vt[(size_t)(n0 + 1) * Bb + b_lo];
        float x10 = g_Vt[(size_t)n0 * Bb + b_hi];
        float x11 = g_Vt[(size_t)(n0 + 1) * Bb + b_hi];
        s0 = fmaf(d[nt][0], x00, fmaf(d[nt][1], x01, s0));
        s1 = fmaf(d[nt][2], x10, fmaf(d[nt][3], x11, s1));
    }
    s0 += __shfl_xor_sync(0xffffffffu, s0, 1);
    s0 += __shfl_xor_sync(0xffffffffu, s0, 2);
    s1 += __shfl_xor_sync(0xffffffffu, s1, 1);
    s1 += __shfl_xor_sync(0xffffffffu, s1, 2);
    if ((lane & 3) == 0) {
        atomicAdd(&g_accum[b_lo], 2.0f * s0);
        atomicAdd(&g_accum[b_hi], 2.0f * s1);
    }

    // ---- last-CTA: publish + reset ----
    __threadfence();
    __syncthreads();
    __shared__ bool last;
    if (tid == 0) last = (atomicAdd(&g_count, 1u) == MAIN_CTAS - 1);
    __syncthreads();
    if (last) {
        __threadfence();
        if (tid < Bb) out[tid] = atomicExch(&g_accum[tid], 0.0f);
        if (tid == 0) atomicExch(&g_count, 0u);
    }
}

extern "C" void kernel_launch(void* const* d_in, const int* in_sizes, int n_in,
                              void* d_out, int out_size)
{
    const float* V = (const float*)d_in[0];   // vector [128,1024]
    const float* W = (const float*)d_in[1];   // interactions [1024,1024]
    float* out = (float*)d_out;               // [128] fp32

    cudaFuncSetAttribute(potts_mma, cudaFuncAttributeMaxDynamicSharedMemorySize, SM_TOT);

    dim3 tg(32, 4), tb(32, 8);
    prep_v<<<tg, tb>>>(V);
    prep_s<<<PREPS_CTAS, 256>>>(W);
    potts_mma<<<MAIN_CTAS, 256, SM_TOT>>>(out);
}